// round 14
// baseline (speedup 1.0000x reference)
#include <cuda_runtime.h>
#include <cuda_fp16.h>
#include <cstdint>
#include <math.h>

#define BB   4
#define SS   2048
#define DMODEL 1024
#define NH   16
#define DKH  64
#define MTOK (BB*SS)   // 8192

// 0.125 * log2(e): folds score scale + exp->exp2 conversion into Q projection
#define QSCALE 0.18033688011112042f

// fp16 scratch (device globals: allocation-free).
__device__ __half g_q16[MTOK * DMODEL];
__device__ __half g_k16[MTOK * DMODEL];
__device__ __half g_v16[MTOK * DMODEL];
__device__ __half g_w16[4 * DMODEL * DMODEL];   // wq, wk, wv, wo
__device__ __half g_Qh [MTOK * DMODEL];
__device__ __half g_Kh [MTOK * DMODEL];
__device__ __half g_Vh [MTOK * DMODEL];
__device__ __half g_Ctx[MTOK * DMODEL];
__device__ __half g_mkh[BB * SS];               // +inf (keep) / -inf (masked)

// ---------------------------------------------------------------------------
// helpers (baseline PTX; no sm_103a-only features)
// ---------------------------------------------------------------------------
__device__ __forceinline__ uint32_t h2pk(float lo, float hi) {
    __half2 h = __halves2half2(__float2half_rn(lo), __float2half_rn(hi));
    return *(uint32_t*)&h;
}

__device__ __forceinline__ uint32_t cvt2h(float hi, float lo) {
    uint32_t r;
    asm("cvt.rn.f16x2.f32 %0, %1, %2;" : "=r"(r) : "f"(hi), "f"(lo));
    return r;
}

__device__ __forceinline__ uint32_t hmin2(uint32_t a, uint32_t b) {
    uint32_t r;
    asm("min.f16x2 %0, %1, %2;" : "=r"(r) : "r"(a), "r"(b));
    return r;
}

__device__ __forceinline__ uint32_t hex2(uint32_t a) {
    uint32_t r;
    asm("ex2.approx.f16x2 %0, %1;" : "=r"(r) : "r"(a));
    return r;
}

__device__ __forceinline__ void mma_16n8k16_f16(float* d, const uint32_t* a,
                                                const uint32_t* b) {
    asm volatile(
        "mma.sync.aligned.m16n8k16.row.col.f32.f16.f16.f32 "
        "{%0,%1,%2,%3}, {%4,%5,%6,%7}, {%8,%9}, {%0,%1,%2,%3};\n"
        : "+f"(d[0]), "+f"(d[1]), "+f"(d[2]), "+f"(d[3])
        : "r"(a[0]), "r"(a[1]), "r"(a[2]), "r"(a[3]),
          "r"(b[0]), "r"(b[1]));
}

__device__ __forceinline__ void ldm_x4(uint32_t* r, uint32_t saddr) {
    asm volatile(
        "ldmatrix.sync.aligned.m8n8.x4.shared.b16 {%0,%1,%2,%3}, [%4];"
        : "=r"(r[0]), "=r"(r[1]), "=r"(r[2]), "=r"(r[3]) : "r"(saddr));
}

__device__ __forceinline__ void ldm_x4_t(uint32_t* r, uint32_t saddr) {
    asm volatile(
        "ldmatrix.sync.aligned.m8n8.x4.trans.shared.b16 {%0,%1,%2,%3}, [%4];"
        : "=r"(r[0]), "=r"(r[1]), "=r"(r[2]), "=r"(r[3]) : "r"(saddr));
}

__device__ __forceinline__ void ldm_x2_t(uint32_t* r, uint32_t saddr) {
    asm volatile(
        "ldmatrix.sync.aligned.m8n8.x2.trans.shared.b16 {%0,%1}, [%2];"
        : "=r"(r[0]), "=r"(r[1]) : "r"(saddr));
}

__device__ __forceinline__ void cp16(uint32_t smem, const void* g) {
    asm volatile("cp.async.cg.shared.global [%0], [%1], 16;\n"
                 :: "r"(smem), "l"(g));
}
#define CP_COMMIT() asm volatile("cp.async.commit_group;\n" ::: "memory")
#define CP_WAIT0()  asm volatile("cp.async.wait_group 0;\n" ::: "memory")
#define CP_WAIT1()  asm volatile("cp.async.wait_group 1;\n" ::: "memory")

// ---------------------------------------------------------------------------
// one-time conversion kernels
// ---------------------------------------------------------------------------
__global__ __launch_bounds__(256)
void cvt_qkv_kernel(const float* __restrict__ q, const float* __restrict__ k,
                    const float* __restrict__ v)
{
    const float* in = (blockIdx.y == 0) ? q : (blockIdx.y == 1) ? k : v;
    __half* out = (blockIdx.y == 0) ? g_q16 : (blockIdx.y == 1) ? g_k16 : g_v16;
    const size_t i = ((size_t)blockIdx.x * 256 + threadIdx.x) * 8;
    float4 a = *(const float4*)(in + i);
    float4 b = *(const float4*)(in + i + 4);
    *(uint4*)(out + i) = make_uint4(h2pk(a.x, a.y), h2pk(a.z, a.w),
                                    h2pk(b.x, b.y), h2pk(b.z, b.w));
}

__global__ __launch_bounds__(256)
void cvt_w_kernel(const float* __restrict__ wq, const float* __restrict__ wk,
                  const float* __restrict__ wv, const float* __restrict__ wo)
{
    const float* in = (blockIdx.y == 0) ? wq : (blockIdx.y == 1) ? wk
                    : (blockIdx.y == 2) ? wv : wo;
    __half* out = g_w16 + (size_t)blockIdx.y * DMODEL * DMODEL;
    const size_t i = ((size_t)blockIdx.x * 256 + threadIdx.x) * 8;
    float4 a = *(const float4*)(in + i);
    float4 b = *(const float4*)(in + i + 4);
    *(uint4*)(out + i) = make_uint4(h2pk(a.x, a.y), h2pk(a.z, a.w),
                                    h2pk(b.x, b.y), h2pk(b.z, b.w));
}

__global__ __launch_bounds__(256)
void cvt_mask_kernel(const int* __restrict__ mask)
{
    const int i = blockIdx.x * 256 + threadIdx.x;   // 8192 total
    const unsigned short bits = mask[i] ? 0x7C00u : 0xFC00u;   // +inf / -inf
    *(unsigned short*)&g_mkh[i] = bits;
}

// ===========================================================================
// GEMM fp16 m16n8k16, CTA 128x256, 8 warps 2(m)x4(n), WARP TILE 64x64
// (8 LDSM.x4 per 32 MMAs per k16 -> 1.5x less smem-crossbar per FLOP).
// 3-stage cp.async pipeline. 1 CTA/SM (reg budget 256).
// ===========================================================================
#define GPH    40
#define ASTGH  (128 * GPH)            // 5120 halves per A stage
#define BSTGH  (256 * GPH)            // 10240 halves per B stage
#define BBASEH (3 * ASTGH)            // B stages start (halves)
#define GEMM_SMEM_BYTES ((3 * ASTGH + 3 * BSTGH) * 2)   // 92160 B

__device__ __forceinline__ void gemm_issue(uint32_t sb, const __half* Ap,
                                           const __half* Bp, int tid,
                                           int k0, int st)
{
    #pragma unroll
    for (int i = 0; i < 2; i++) {
        const int fi  = tid + 256 * i;      // 0..511
        const int row = fi >> 2;            // 0..127
        const int c   = fi & 3;
        cp16(sb + (uint32_t)((st * ASTGH + row * GPH + c * 8) * 2),
             Ap + (size_t)row * DMODEL + k0 + c * 8);
    }
    #pragma unroll
    for (int i = 0; i < 4; i++) {
        const int fi  = tid + 256 * i;      // 0..1023
        const int row = fi >> 2;            // 0..255
        const int c   = fi & 3;
        cp16(sb + (uint32_t)((BBASEH + st * BSTGH + row * GPH + c * 8) * 2),
             Bp + (size_t)row * DMODEL + k0 + c * 8);
    }
}

// MODE 0: fp32 flat out. MODE 1: fp16 head-split out (scaled by outscale).
template<int MODE>
__device__ __forceinline__ void gemm_core(const __half* __restrict__ X,
                                          const __half* __restrict__ W,
                                          const float* __restrict__ bias,
                                          void* __restrict__ outv,
                                          float outscale,
                                          __half* smh)
{
    const int tid  = threadIdx.x;
    const int wid  = tid >> 5;
    const int lane = tid & 31;
    const int gid  = lane >> 2;
    const int tig  = lane & 3;
    const int wm   = wid >> 2;          // 0..1 -> m offset wm*64
    const int wn   = wid & 3;           // 0..3 -> n offset wn*64
    const int lr   = lane & 15;
    const int lc8  = (lane >> 4) * 8;

    const int m0 = blockIdx.x * 128;
    const int n0 = blockIdx.y * 256;

    const __half* Ap = X + (size_t)m0 * DMODEL;
    const __half* Bp = W + (size_t)n0 * DMODEL;

    const uint32_t sbase = (uint32_t)__cvta_generic_to_shared(smh);
    uint32_t aoff[4], boff[4];
    #pragma unroll
    for (int mi = 0; mi < 4; mi++)
        aoff[mi] = (uint32_t)(((wm * 64 + mi * 16 + lr) * GPH + lc8) * 2);
    #pragma unroll
    for (int njp = 0; njp < 4; njp++)
        boff[njp] = (uint32_t)((BBASEH + (wn * 64 + njp * 16 + lr) * GPH + lc8) * 2);

    float acc[4][8][4];
    #pragma unroll
    for (int mi = 0; mi < 4; mi++)
        #pragma unroll
        for (int nj = 0; nj < 8; nj++)
            #pragma unroll
            for (int c = 0; c < 4; c++) acc[mi][nj][c] = 0.f;

    gemm_issue(sbase, Ap, Bp, tid, 0, 0);  CP_COMMIT();
    gemm_issue(sbase, Ap, Bp, tid, 32, 1); CP_COMMIT();

    for (int s = 0; s < 32; s++) {
        if (s + 1 < 32) { CP_WAIT1(); } else { CP_WAIT0(); }
        __syncthreads();
        if (s + 2 < 32) {
            gemm_issue(sbase, Ap, Bp, tid, (s + 2) * 32, (s + 2) % 3);
            CP_COMMIT();
        }

        const int st = s % 3;
        const uint32_t abuf = sbase + (uint32_t)(st * ASTGH * 2);
        const uint32_t bbuf = sbase + (uint32_t)(st * BSTGH * 2);

        #pragma unroll
        for (int k16 = 0; k16 < 2; k16++) {
            const uint32_t kb = (uint32_t)(k16 * 32);
            uint32_t af[4][4];
            #pragma unroll
            for (int mi = 0; mi < 4; mi++)
                ldm_x4(af[mi], abuf + aoff[mi] + kb);
            uint32_t bfm[4][4];
            #pragma unroll
            for (int njp = 0; njp < 4; njp++)
                ldm_x4(bfm[njp], bbuf + boff[njp] + kb);
            #pragma unroll
            for (int njp = 0; njp < 4; njp++) {
                uint32_t b0[2] = { bfm[njp][0], bfm[njp][2] };
                uint32_t b1[2] = { bfm[njp][1], bfm[njp][3] };
                #pragma unroll
                for (int mi = 0; mi < 4; mi++) {
                    mma_16n8k16_f16(acc[mi][2 * njp    ], af[mi], b0);
                    mma_16n8k16_f16(acc[mi][2 * njp + 1], af[mi], b1);
                }
            }
        }
    }

    #pragma unroll
    for (int mi = 0; mi < 4; mi++) {
        #pragma unroll
        for (int half = 0; half < 2; half++) {
            const int m = m0 + wm * 64 + mi * 16 + gid + half * 8;
            #pragma unroll
            for (int nj = 0; nj < 8; nj++) {
                const int n = n0 + wn * 64 + nj * 8 + tig * 2;
                float ox = acc[mi][nj][half * 2 + 0] + __ldg(&bias[n + 0]);
                float oy = acc[mi][nj][half * 2 + 1] + __ldg(&bias[n + 1]);
                if (MODE == 0) {
                    float* dst = (float*)outv + (size_t)m * DMODEL + n;
                    *(float2*)dst = make_float2(ox, oy);
                } else {
                    ox *= outscale; oy *= outscale;
                    const int b = m >> 11, s2 = m & (SS - 1);
                    const int h = n >> 6,  d  = n & (DKH - 1);
                    __half* dst = (__half*)outv +
                        (((size_t)(b * NH + h) * SS) + s2) * DKH + d;
                    *(uint32_t*)dst = h2pk(ox, oy);
                }
            }
        }
    }
}

__global__ __launch_bounds__(256, 1)
void gemm_qkv_kernel(const float* __restrict__ bq, const float* __restrict__ bk,
                     const float* __restrict__ bv)
{
    extern __shared__ __half smg[];
    const int z = blockIdx.z;
    const __half* X = (z == 0) ? g_q16 : (z == 1) ? g_k16 : g_v16;
    const __half* W = g_w16 + (size_t)z * DMODEL * DMODEL;
    const float* B = (z == 0) ? bq : (z == 1) ? bk : bv;
    __half* O = (z == 0) ? g_Qh : (z == 1) ? g_Kh : g_Vh;
    const float sc = (z == 0) ? QSCALE : 1.0f;
    gemm_core<1>(X, W, B, O, sc, smg);
}

__global__ __launch_bounds__(256, 1)
void gemm_out_kernel(const float* __restrict__ bias, float* __restrict__ out)
{
    extern __shared__ __half smg[];
    gemm_core<0>(g_Ctx, g_w16 + (size_t)3 * DMODEL * DMODEL, bias, out, 1.0f, smg);
}

// ===========================================================================
// Flash attention fp16 m16n8k16, static-C softmax, mask via min.f16x2,
// p = ex2.approx.f16x2 into A-frag, row sums via ones-column MMA.
// cp.async double-buffered K/V+mask; 1 sync/tile.  (R11-best config.)
// ===========================================================================
#define FQ  128
#define FK  64
#define AP2 72
#define QTILE (FQ*AP2)                // 9216 halves
#define KTILE (FK*AP2)                // 4608 halves
#define SM_QS 0
#define SM_KS QTILE                   // 9216
#define SM_VS (SM_KS + 2*KTILE)       // 18432
#define SM_MK (SM_VS + 2*KTILE)       // 27648 halves
#define ATTN2_SMEM_BYTES ((SM_MK + 128) * 2 + 256)

__device__ __forceinline__ void attn_issue(uint32_t sb, const __half* Kb,
                                           const __half* Vb, const __half* mb,
                                           int tid, int kt, int buf)
{
    #pragma unroll
    for (int i = 0; i < 2; i++) {
        const int fi  = tid + 256 * i;
        const int row = fi >> 3;
        const int c   = fi & 7;
        cp16(sb + (uint32_t)((SM_KS + buf * KTILE + row * AP2 + c * 8) * 2),
             Kb + (size_t)(kt * FK + row) * DKH + c * 8);
        cp16(sb + (uint32_t)((SM_VS + buf * KTILE + row * AP2 + c * 8) * 2),
             Vb + (size_t)(kt * FK + row) * DKH + c * 8);
    }
    if (tid < 8)
        cp16(sb + (uint32_t)((SM_MK + buf * 64 + tid * 8) * 2),
             mb + kt * 64 + tid * 8);
}

__global__ __launch_bounds__(256, 2)
void flash_attn_mma_kernel()
{
    extern __shared__ __half smh[];
    __half* mskh = smh + SM_MK;       // mskh[buf*64 + c], +-inf

    const int qt = blockIdx.x;
    const int bh = blockIdx.y;
    const int b  = bh >> 4;
    const int h  = bh & 15;

    const __half* Qb = g_Qh + (size_t)bh * SS * DKH;
    const __half* Kb = g_Kh + (size_t)bh * SS * DKH;
    const __half* Vb = g_Vh + (size_t)bh * SS * DKH;
    const __half* mb = g_mkh + b * SS;

    const int tid  = threadIdx.x;
    const int wid  = tid >> 5;
    const int lane = tid & 31;
    const int gid  = lane >> 2;
    const int tig  = lane & 3;
    const int r0   = wid * 16 + gid;
    const int r1   = r0 + 8;
    const int lr   = lane & 15;
    const int lc8  = (lane >> 4) * 8;

    const uint32_t sbase = (uint32_t)__cvta_generic_to_shared(smh);
    const uint32_t qoff  = sbase + (uint32_t)(((wid * 16 + lr) * AP2 + lc8) * 2);
    uint32_t koff[4];
    #pragma unroll
    for (int nbp = 0; nbp < 4; nbp++)
        koff[nbp] = (uint32_t)(((nbp * 16 + lr) * AP2 + lc8) * 2);
    const int vg  = lane >> 3;
    const int vl7 = lane & 7;
    const uint32_t voff  = (uint32_t)((((vg & 1) * 8 + vl7) * AP2 + (vg >> 1) * 8) * 2);
    const uint32_t voff1 = (uint32_t)((((vg & 1) * 8 + vl7) * AP2 + 64) * 2);

    // prologue: tile 0 via cp.async
    attn_issue(sbase, Kb, Vb, mb, tid, 0, 0);
    CP_COMMIT();

    // Q tile copy (fp16, pre-scaled by QSCALE in projection)
    #pragma unroll
    for (int i = 0; i < 4; i++) {
        const int fi  = tid + 256 * i;
        const int row = fi >> 3;
        const int c   = fi & 7;
        *(uint4*)&smh[SM_QS + (size_t)row * AP2 + c * 8] =
            *(const uint4*)(Qb + (size_t)(qt * FQ + row) * DKH + c * 8);
    }
    // ones padding in V cols 64..71 (both buffers) — row-sum column
    {
        const uint32_t one2 = 0x3C003C00u;   // half2(1.0, 1.0)
        for (int i = tid; i < 2 * FK * 4; i += 256) {
            const int buf = i >> 8;
            const int row = (i >> 2) & 63;
            const int c2  = i & 3;
            *(uint32_t*)&smh[SM_VS + buf * KTILE + row * AP2 + 64 + c2 * 2] = one2;
        }
    }

    float o[8][4], o9[4];
    #pragma unroll
    for (int nb = 0; nb < 8; nb++)
        #pragma unroll
        for (int c = 0; c < 4; c++) o[nb][c] = 0.f;
    #pragma unroll
    for (int c = 0; c < 4; c++) o9[c] = 0.f;

    const int NT = SS / FK;   // 32
    for (int kt = 0; kt < NT; kt++) {
        const int cur = kt & 1;
        CP_WAIT0();
        __syncthreads();
        if (kt + 1 < NT) {
            attn_issue(sbase, Kb, Vb, mb, tid, kt + 1, 1 - cur);
            CP_COMMIT();
        }

        const uint32_t kbase = sbase + (uint32_t)((SM_KS + cur * KTILE) * 2);
        const uint32_t vbase = sbase + (uint32_t)((SM_VS + cur * KTILE) * 2);
        const __half* mc = mskh + cur * 64;

        // ---- S = Q K^T (log2 domain) ----
        float sa[8][4];
        #pragma unroll
        for (int nb = 0; nb < 8; nb++)
            #pragma unroll
            for (int c = 0; c < 4; c++) sa[nb][c] = 0.f;

        #pragma unroll
        for (int k16 = 0; k16 < 4; k16++) {
            const uint32_t kb = (uint32_t)(k16 * 32);
            uint32_t af[4];
            ldm_x4(af, qoff + kb);
            #pragma unroll
            for (int nbp = 0; nbp < 4; nbp++) {
                uint32_t bfm[4];
                ldm_x4(bfm, kbase + koff[nbp] + kb);
                uint32_t b0[2] = { bfm[0], bfm[2] };
                uint32_t b1[2] = { bfm[1], bfm[3] };
                mma_16n8k16_f16(sa[2 * nbp    ], af, b0);
                mma_16n8k16_f16(sa[2 * nbp + 1], af, b1);
            }
        }

        // ---- static-C softmax: p = exp2(min(s, maskinf)), packed fp16x2 ----
        uint32_t pfrag[4][4];
        #pragma unroll
        for (int nb = 0; nb < 8; nb++) {
            const int c0 = nb * 8 + 2 * tig;
            const uint32_t m2 = *(const uint32_t*)&mc[c0];   // half2 +-inf
            uint32_t s0 = cvt2h(sa[nb][1], sa[nb][0]);       // row r0 pair
            uint32_t s1 = cvt2h(sa[nb][3], sa[nb][2]);       // row r1 pair
            const uint32_t p0 = hex2(hmin2(s0, m2));
            const uint32_t p1 = hex2(hmin2(s1, m2));
            const int kb2 = nb >> 1;
            if ((nb & 1) == 0) {
                pfrag[kb2][0] = p0;
                pfrag[kb2][1] = p1;
            } else {
                pfrag[kb2][2] = p0;
                pfrag[kb2][3] = p1;
            }
        }

        // ---- O += P V ; row sums accumulate into o9 via ones-column ----
        #pragma unroll
        for (int k16 = 0; k16 < 4; k16++) {
            const uint32_t krow = (uint32_t)(k16 * 16 * AP2 * 2);
            #pragma unroll
            for (int db = 0; db < 4; db++) {
                uint32_t vfm[4];
                ldm_x4_t(vfm, vbase + voff + krow + (uint32_t)(db * 32));
                uint32_t b0[2] = { vfm[0], vfm[1] };
                uint32_t b1[2] = { vfm[2], vfm[3] };
                mma_16n8k16_f16(o[2 * db    ], pfrag[k16], b0);
                mma_16n8k16_f16(o[2 * db + 1], pfrag[k16], b1);
            }
            uint32_t ofm[2];
            ldm_x2_t(ofm, vbase + voff1 + krow);
            mma_16n8k16_f16(o9, pfrag[k16], ofm);
        }
    }

    // ---- epilogue: l from ones-column, fp16 Ctx ----
    const float inv0 = 1.f / o9[0];
    const float inv1 = 1.f / o9[2];
    const int grow0 = qt * FQ + r0;
    const int grow1 = qt * FQ + r1;
    #pragma unroll
    for (int nb = 0; nb < 8; nb++) {
        const int d = nb * 8 + 2 * tig;
        *(uint32_t*)&g_Ctx[((size_t)(b * SS + grow0)) * DMODEL + h * DKH + d] =
            h2pk(o[nb][0] * inv0, o[nb][1] * inv0);
        *(uint32_t*)&g_Ctx[((size_t)(b * SS + grow1)) * DMODEL + h * DKH + d] =
            h2pk(o[nb][2] * inv1, o[nb][3] * inv1);
    }
}

// ---------------------------------------------------------------------------
extern "C" void kernel_launch(void* const* d_in, const int* in_sizes, int n_in,
                              void* d_out, int out_size)
{
    const float* q    = (const float*)d_in[0];
    const float* k    = (const float*)d_in[1];
    const float* v    = (const float*)d_in[2];
    const int*   mask = (const int*)  d_in[3];
    const float* wq   = (const float*)d_in[4];
    const float* bq   = (const float*)d_in[5];
    const float* wk   = (const float*)d_in[6];
    const float* bk   = (const float*)d_in[7];
    const float* wv   = (const float*)d_in[8];
    const float* bv   = (const float*)d_in[9];
    const float* wo   = (const float*)d_in[10];
    const float* bo   = (const float*)d_in[11];
    float* out = (float*)d_out;

    (void)cudaFuncSetAttribute(flash_attn_mma_kernel,
                               cudaFuncAttributeMaxDynamicSharedMemorySize,
                               ATTN2_SMEM_BYTES);
    (void)cudaFuncSetAttribute(gemm_qkv_kernel,
                               cudaFuncAttributeMaxDynamicSharedMemorySize,
                               GEMM_SMEM_BYTES);
    (void)cudaFuncSetAttribute(gemm_out_kernel,
                               cudaFuncAttributeMaxDynamicSharedMemorySize,
                               GEMM_SMEM_BYTES);

    dim3 gc1(MTOK * DMODEL / (256 * 8), 3);   // (4096, 3)
    cvt_qkv_kernel<<<gc1, 256>>>(q, k, v);
    dim3 gc2(DMODEL * DMODEL / (256 * 8), 4); // (512, 4)
    cvt_w_kernel<<<gc2, 256>>>(wq, wk, wv, wo);
    cvt_mask_kernel<<<BB * SS / 256, 256>>>(mask);

    dim3 gq(MTOK/128, DMODEL/256, 3);   // (64, 4, 3)
    gemm_qkv_kernel<<<gq, 256, GEMM_SMEM_BYTES>>>(bq, bk, bv);

    dim3 ga(SS/FQ, BB*NH);              // (16, 64)
    flash_attn_mma_kernel<<<ga, 256, ATTN2_SMEM_BYTES>>>();

    dim3 gg(MTOK/128, DMODEL/256);      // (64, 4)
    gemm_out_kernel<<<gg, 256, GEMM_SMEM_BYTES>>>(bo, out);
}

// round 15
// speedup vs baseline: 1.1496x; 1.1496x over previous
#include <cuda_runtime.h>
#include <cuda_fp16.h>
#include <cstdint>
#include <math.h>

#define BB   4
#define SS   2048
#define DMODEL 1024
#define NH   16
#define DKH  64
#define MTOK (BB*SS)   // 8192

// 0.125 * log2(e): folds score scale + exp->exp2 conversion into Q projection
#define QSCALE 0.18033688011112042f

// fp16 scratch (device globals: allocation-free).
__device__ __half g_q16[MTOK * DMODEL];
__device__ __half g_k16[MTOK * DMODEL];
__device__ __half g_v16[MTOK * DMODEL];
__device__ __half g_w16[4 * DMODEL * DMODEL];   // wq, wk, wv, wo
__device__ __half g_Qh [MTOK * DMODEL];
__device__ __half g_Kh [MTOK * DMODEL];
__device__ __half g_Vh [MTOK * DMODEL];
__device__ __half g_Ctx[MTOK * DMODEL];
__device__ __half g_mkh[BB * SS];               // +inf (keep) / -inf (masked)

// ---------------------------------------------------------------------------
// helpers (baseline PTX; no sm_103a-only features)
// ---------------------------------------------------------------------------
__device__ __forceinline__ uint32_t h2pk(float lo, float hi) {
    __half2 h = __halves2half2(__float2half_rn(lo), __float2half_rn(hi));
    return *(uint32_t*)&h;
}

__device__ __forceinline__ uint32_t cvt2h(float hi, float lo) {
    uint32_t r;
    asm("cvt.rn.f16x2.f32 %0, %1, %2;" : "=r"(r) : "f"(hi), "f"(lo));
    return r;
}

__device__ __forceinline__ uint32_t hmin2(uint32_t a, uint32_t b) {
    uint32_t r;
    asm("min.f16x2 %0, %1, %2;" : "=r"(r) : "r"(a), "r"(b));
    return r;
}

__device__ __forceinline__ uint32_t hex2(uint32_t a) {
    uint32_t r;
    asm("ex2.approx.f16x2 %0, %1;" : "=r"(r) : "r"(a));
    return r;
}

__device__ __forceinline__ void mma_16n8k16_f16(float* d, const uint32_t* a,
                                                const uint32_t* b) {
    asm volatile(
        "mma.sync.aligned.m16n8k16.row.col.f32.f16.f16.f32 "
        "{%0,%1,%2,%3}, {%4,%5,%6,%7}, {%8,%9}, {%0,%1,%2,%3};\n"
        : "+f"(d[0]), "+f"(d[1]), "+f"(d[2]), "+f"(d[3])
        : "r"(a[0]), "r"(a[1]), "r"(a[2]), "r"(a[3]),
          "r"(b[0]), "r"(b[1]));
}

__device__ __forceinline__ void ldm_x4(uint32_t* r, uint32_t saddr) {
    asm volatile(
        "ldmatrix.sync.aligned.m8n8.x4.shared.b16 {%0,%1,%2,%3}, [%4];"
        : "=r"(r[0]), "=r"(r[1]), "=r"(r[2]), "=r"(r[3]) : "r"(saddr));
}

__device__ __forceinline__ void ldm_x4_t(uint32_t* r, uint32_t saddr) {
    asm volatile(
        "ldmatrix.sync.aligned.m8n8.x4.trans.shared.b16 {%0,%1,%2,%3}, [%4];"
        : "=r"(r[0]), "=r"(r[1]), "=r"(r[2]), "=r"(r[3]) : "r"(saddr));
}

__device__ __forceinline__ void ldm_x2_t(uint32_t* r, uint32_t saddr) {
    asm volatile(
        "ldmatrix.sync.aligned.m8n8.x2.trans.shared.b16 {%0,%1}, [%2];"
        : "=r"(r[0]), "=r"(r[1]) : "r"(saddr));
}

__device__ __forceinline__ void cp16(uint32_t smem, const void* g) {
    asm volatile("cp.async.cg.shared.global [%0], [%1], 16;\n"
                 :: "r"(smem), "l"(g));
}
#define CP_COMMIT() asm volatile("cp.async.commit_group;\n" ::: "memory")
#define CP_WAIT0()  asm volatile("cp.async.wait_group 0;\n" ::: "memory")

// ---------------------------------------------------------------------------
// one-time conversion kernels
// ---------------------------------------------------------------------------
__global__ __launch_bounds__(256)
void cvt_qkv_kernel(const float* __restrict__ q, const float* __restrict__ k,
                    const float* __restrict__ v)
{
    const float* in = (blockIdx.y == 0) ? q : (blockIdx.y == 1) ? k : v;
    __half* out = (blockIdx.y == 0) ? g_q16 : (blockIdx.y == 1) ? g_k16 : g_v16;
    const size_t i = ((size_t)blockIdx.x * 256 + threadIdx.x) * 8;
    float4 a = *(const float4*)(in + i);
    float4 b = *(const float4*)(in + i + 4);
    *(uint4*)(out + i) = make_uint4(h2pk(a.x, a.y), h2pk(a.z, a.w),
                                    h2pk(b.x, b.y), h2pk(b.z, b.w));
}

__global__ __launch_bounds__(256)
void cvt_w_kernel(const float* __restrict__ wq, const float* __restrict__ wk,
                  const float* __restrict__ wv, const float* __restrict__ wo)
{
    const float* in = (blockIdx.y == 0) ? wq : (blockIdx.y == 1) ? wk
                    : (blockIdx.y == 2) ? wv : wo;
    __half* out = g_w16 + (size_t)blockIdx.y * DMODEL * DMODEL;
    const size_t i = ((size_t)blockIdx.x * 256 + threadIdx.x) * 8;
    float4 a = *(const float4*)(in + i);
    float4 b = *(const float4*)(in + i + 4);
    *(uint4*)(out + i) = make_uint4(h2pk(a.x, a.y), h2pk(a.z, a.w),
                                    h2pk(b.x, b.y), h2pk(b.z, b.w));
}

__global__ __launch_bounds__(256)
void cvt_mask_kernel(const int* __restrict__ mask)
{
    const int i = blockIdx.x * 256 + threadIdx.x;   // 8192 total
    const unsigned short bits = mask[i] ? 0x7C00u : 0xFC00u;   // +inf / -inf
    *(unsigned short*)&g_mkh[i] = bits;
}

// ===========================================================================
// GEMM fp16 m16n8k16, BK=64 (16 stages -> HALF the barriers of BK=32),
// double-buffered cp.async, ldmatrix frags.
// CTA 128x128, 8 warps 4(m)x2(n), warp 32x64. Smem stride 72 halves (144 B).
// ===========================================================================
#define GPH   72
#define GSTG  (128 * GPH)             // 9216 halves per operand-stage
#define GEMM_SMEM_BYTES (4 * GSTG * 2)   // A0,A1,B0,B1 = 73728 B

__device__ __forceinline__ void gemm_issue(uint32_t sb, const __half* Ap,
                                           const __half* Bp, int tid,
                                           int k0, int st)
{
    #pragma unroll
    for (int i = 0; i < 4; i++) {
        const int fi  = tid + 256 * i;      // 0..1023
        const int row = fi >> 3;            // 0..127
        const int c   = fi & 7;             // 8 halves per chunk
        cp16(sb + (uint32_t)((st * GSTG + row * GPH + c * 8) * 2),
             Ap + (size_t)row * DMODEL + k0 + c * 8);
        cp16(sb + (uint32_t)(((2 + st) * GSTG + row * GPH + c * 8) * 2),
             Bp + (size_t)row * DMODEL + k0 + c * 8);
    }
}

// MODE 0: fp32 flat out. MODE 1: fp16 head-split out (scaled by outscale).
template<int MODE>
__device__ __forceinline__ void gemm_core(const __half* __restrict__ X,
                                          const __half* __restrict__ W,
                                          const float* __restrict__ bias,
                                          void* __restrict__ outv,
                                          float outscale,
                                          __half* smh)
{
    const int tid  = threadIdx.x;
    const int wid  = tid >> 5;
    const int lane = tid & 31;
    const int gid  = lane >> 2;
    const int tig  = lane & 3;
    const int wm   = wid >> 1;
    const int wn   = wid & 1;
    const int lr   = lane & 15;
    const int lc8  = (lane >> 4) * 8;

    const int m0 = blockIdx.x * 128;
    const int n0 = blockIdx.y * 128;

    const __half* Ap = X + (size_t)m0 * DMODEL;
    const __half* Bp = W + (size_t)n0 * DMODEL;

    const uint32_t sbase = (uint32_t)__cvta_generic_to_shared(smh);
    uint32_t aoff[2], boff[4];
    #pragma unroll
    for (int mi = 0; mi < 2; mi++)
        aoff[mi] = (uint32_t)(((wm * 32 + mi * 16 + lr) * GPH + lc8) * 2);
    #pragma unroll
    for (int njp = 0; njp < 4; njp++)
        boff[njp] = (uint32_t)((2 * GSTG + (wn * 64 + njp * 16 + lr) * GPH + lc8) * 2);

    float acc[2][8][4];
    #pragma unroll
    for (int mi = 0; mi < 2; mi++)
        #pragma unroll
        for (int nj = 0; nj < 8; nj++)
            #pragma unroll
            for (int c = 0; c < 4; c++) acc[mi][nj][c] = 0.f;

    gemm_issue(sbase, Ap, Bp, tid, 0, 0);
    CP_COMMIT();

    for (int s = 0; s < 16; s++) {
        CP_WAIT0();
        __syncthreads();
        if (s + 1 < 16) {
            gemm_issue(sbase, Ap, Bp, tid, (s + 1) * 64, (s + 1) & 1);
            CP_COMMIT();
        }

        const int st = s & 1;
        const uint32_t abuf = sbase + (uint32_t)(st * GSTG * 2);
        const uint32_t bb   = (uint32_t)(st * GSTG * 2);

        #pragma unroll
        for (int k16 = 0; k16 < 4; k16++) {
            const uint32_t kb = (uint32_t)(k16 * 32);
            uint32_t af[2][4];
            ldm_x4(af[0], abuf + aoff[0] + kb);
            ldm_x4(af[1], abuf + aoff[1] + kb);
            #pragma unroll
            for (int njp = 0; njp < 4; njp++) {
                uint32_t bfm[4];
                ldm_x4(bfm, sbase + bb + boff[njp] + kb);
                uint32_t b0[2] = { bfm[0], bfm[2] };
                uint32_t b1[2] = { bfm[1], bfm[3] };
                mma_16n8k16_f16(acc[0][2 * njp    ], af[0], b0);
                mma_16n8k16_f16(acc[1][2 * njp    ], af[1], b0);
                mma_16n8k16_f16(acc[0][2 * njp + 1], af[0], b1);
                mma_16n8k16_f16(acc[1][2 * njp + 1], af[1], b1);
            }
        }
    }

    #pragma unroll
    for (int mi = 0; mi < 2; mi++) {
        #pragma unroll
        for (int half = 0; half < 2; half++) {
            const int m = m0 + wm * 32 + mi * 16 + gid + half * 8;
            #pragma unroll
            for (int nj = 0; nj < 8; nj++) {
                const int n = n0 + wn * 64 + nj * 8 + tig * 2;
                float ox = acc[mi][nj][half * 2 + 0] + __ldg(&bias[n + 0]);
                float oy = acc[mi][nj][half * 2 + 1] + __ldg(&bias[n + 1]);
                if (MODE == 0) {
                    float* dst = (float*)outv + (size_t)m * DMODEL + n;
                    *(float2*)dst = make_float2(ox, oy);
                } else {
                    ox *= outscale; oy *= outscale;
                    const int b = m >> 11, s2 = m & (SS - 1);
                    const int h = n >> 6,  d  = n & (DKH - 1);
                    __half* dst = (__half*)outv +
                        (((size_t)(b * NH + h) * SS) + s2) * DKH + d;
                    *(uint32_t*)dst = h2pk(ox, oy);
                }
            }
        }
    }
}

__global__ __launch_bounds__(256, 2)
void gemm_qkv_kernel(const float* __restrict__ bq, const float* __restrict__ bk,
                     const float* __restrict__ bv)
{
    extern __shared__ __half smg[];
    const int z = blockIdx.z;
    const __half* X = (z == 0) ? g_q16 : (z == 1) ? g_k16 : g_v16;
    const __half* W = g_w16 + (size_t)z * DMODEL * DMODEL;
    const float* B = (z == 0) ? bq : (z == 1) ? bk : bv;
    __half* O = (z == 0) ? g_Qh : (z == 1) ? g_Kh : g_Vh;
    const float sc = (z == 0) ? QSCALE : 1.0f;
    gemm_core<1>(X, W, B, O, sc, smg);
}

__global__ __launch_bounds__(256, 2)
void gemm_out_kernel(const float* __restrict__ bias, float* __restrict__ out)
{
    extern __shared__ __half smg[];
    gemm_core<0>(g_Ctx, g_w16 + (size_t)3 * DMODEL * DMODEL, bias, out, 1.0f, smg);
}

// ===========================================================================
// Flash attention fp16 m16n8k16, static-C softmax, mask via min.f16x2,
// p = ex2.approx.f16x2 into A-frag, row sums via ones-column MMA.
// cp.async double-buffered K/V+mask; 1 sync/tile.  (R11-best config.)
// ===========================================================================
#define FQ  128
#define FK  64
#define AP2 72
#define QTILE (FQ*AP2)                // 9216 halves
#define KTILE (FK*AP2)                // 4608 halves
#define SM_QS 0
#define SM_KS QTILE                   // 9216
#define SM_VS (SM_KS + 2*KTILE)       // 18432
#define SM_MK (SM_VS + 2*KTILE)       // 27648 halves
#define ATTN2_SMEM_BYTES ((SM_MK + 128) * 2 + 256)

__device__ __forceinline__ void attn_issue(uint32_t sb, const __half* Kb,
                                           const __half* Vb, const __half* mb,
                                           int tid, int kt, int buf)
{
    #pragma unroll
    for (int i = 0; i < 2; i++) {
        const int fi  = tid + 256 * i;
        const int row = fi >> 3;
        const int c   = fi & 7;
        cp16(sb + (uint32_t)((SM_KS + buf * KTILE + row * AP2 + c * 8) * 2),
             Kb + (size_t)(kt * FK + row) * DKH + c * 8);
        cp16(sb + (uint32_t)((SM_VS + buf * KTILE + row * AP2 + c * 8) * 2),
             Vb + (size_t)(kt * FK + row) * DKH + c * 8);
    }
    if (tid < 8)
        cp16(sb + (uint32_t)((SM_MK + buf * 64 + tid * 8) * 2),
             mb + kt * 64 + tid * 8);
}

__global__ __launch_bounds__(256, 2)
void flash_attn_mma_kernel()
{
    extern __shared__ __half smh[];
    __half* mskh = smh + SM_MK;       // mskh[buf*64 + c], +-inf

    const int qt = blockIdx.x;
    const int bh = blockIdx.y;
    const int b  = bh >> 4;
    const int h  = bh & 15;

    const __half* Qb = g_Qh + (size_t)bh * SS * DKH;
    const __half* Kb = g_Kh + (size_t)bh * SS * DKH;
    const __half* Vb = g_Vh + (size_t)bh * SS * DKH;
    const __half* mb = g_mkh + b * SS;

    const int tid  = threadIdx.x;
    const int wid  = tid >> 5;
    const int lane = tid & 31;
    const int gid  = lane >> 2;
    const int tig  = lane & 3;
    const int r0   = wid * 16 + gid;
    const int r1   = r0 + 8;
    const int lr   = lane & 15;
    const int lc8  = (lane >> 4) * 8;

    const uint32_t sbase = (uint32_t)__cvta_generic_to_shared(smh);
    const uint32_t qoff  = sbase + (uint32_t)(((wid * 16 + lr) * AP2 + lc8) * 2);
    uint32_t koff[4];
    #pragma unroll
    for (int nbp = 0; nbp < 4; nbp++)
        koff[nbp] = (uint32_t)(((nbp * 16 + lr) * AP2 + lc8) * 2);
    const int vg  = lane >> 3;
    const int vl7 = lane & 7;
    const uint32_t voff  = (uint32_t)((((vg & 1) * 8 + vl7) * AP2 + (vg >> 1) * 8) * 2);
    const uint32_t voff1 = (uint32_t)((((vg & 1) * 8 + vl7) * AP2 + 64) * 2);

    // prologue: tile 0 via cp.async
    attn_issue(sbase, Kb, Vb, mb, tid, 0, 0);
    CP_COMMIT();

    // Q tile copy (fp16, pre-scaled by QSCALE in projection)
    #pragma unroll
    for (int i = 0; i < 4; i++) {
        const int fi  = tid + 256 * i;
        const int row = fi >> 3;
        const int c   = fi & 7;
        *(uint4*)&smh[SM_QS + (size_t)row * AP2 + c * 8] =
            *(const uint4*)(Qb + (size_t)(qt * FQ + row) * DKH + c * 8);
    }
    // ones padding in V cols 64..71 (both buffers) — row-sum column
    {
        const uint32_t one2 = 0x3C003C00u;   // half2(1.0, 1.0)
        for (int i = tid; i < 2 * FK * 4; i += 256) {
            const int buf = i >> 8;
            const int row = (i >> 2) & 63;
            const int c2  = i & 3;
            *(uint32_t*)&smh[SM_VS + buf * KTILE + row * AP2 + 64 + c2 * 2] = one2;
        }
    }

    float o[8][4], o9[4];
    #pragma unroll
    for (int nb = 0; nb < 8; nb++)
        #pragma unroll
        for (int c = 0; c < 4; c++) o[nb][c] = 0.f;
    #pragma unroll
    for (int c = 0; c < 4; c++) o9[c] = 0.f;

    const int NT = SS / FK;   // 32
    for (int kt = 0; kt < NT; kt++) {
        const int cur = kt & 1;
        CP_WAIT0();
        __syncthreads();
        if (kt + 1 < NT) {
            attn_issue(sbase, Kb, Vb, mb, tid, kt + 1, 1 - cur);
            CP_COMMIT();
        }

        const uint32_t kbase = sbase + (uint32_t)((SM_KS + cur * KTILE) * 2);
        const uint32_t vbase = sbase + (uint32_t)((SM_VS + cur * KTILE) * 2);
        const __half* mc = mskh + cur * 64;

        // ---- S = Q K^T (log2 domain) ----
        float sa[8][4];
        #pragma unroll
        for (int nb = 0; nb < 8; nb++)
            #pragma unroll
            for (int c = 0; c < 4; c++) sa[nb][c] = 0.f;

        #pragma unroll
        for (int k16 = 0; k16 < 4; k16++) {
            const uint32_t kb = (uint32_t)(k16 * 32);
            uint32_t af[4];
            ldm_x4(af, qoff + kb);
            #pragma unroll
            for (int nbp = 0; nbp < 4; nbp++) {
                uint32_t bfm[4];
                ldm_x4(bfm, kbase + koff[nbp] + kb);
                uint32_t b0[2] = { bfm[0], bfm[2] };
                uint32_t b1[2] = { bfm[1], bfm[3] };
                mma_16n8k16_f16(sa[2 * nbp    ], af, b0);
                mma_16n8k16_f16(sa[2 * nbp + 1], af, b1);
            }
        }

        // ---- static-C softmax: p = exp2(min(s, maskinf)), packed fp16x2 ----
        uint32_t pfrag[4][4];
        #pragma unroll
        for (int nb = 0; nb < 8; nb++) {
            const int c0 = nb * 8 + 2 * tig;
            const uint32_t m2 = *(const uint32_t*)&mc[c0];   // half2 +-inf
            uint32_t s0 = cvt2h(sa[nb][1], sa[nb][0]);       // row r0 pair
            uint32_t s1 = cvt2h(sa[nb][3], sa[nb][2]);       // row r1 pair
            const uint32_t p0 = hex2(hmin2(s0, m2));
            const uint32_t p1 = hex2(hmin2(s1, m2));
            const int kb2 = nb >> 1;
            if ((nb & 1) == 0) {
                pfrag[kb2][0] = p0;
                pfrag[kb2][1] = p1;
            } else {
                pfrag[kb2][2] = p0;
                pfrag[kb2][3] = p1;
            }
        }

        // ---- O += P V ; row sums accumulate into o9 via ones-column ----
        #pragma unroll
        for (int k16 = 0; k16 < 4; k16++) {
            const uint32_t krow = (uint32_t)(k16 * 16 * AP2 * 2);
            #pragma unroll
            for (int db = 0; db < 4; db++) {
                uint32_t vfm[4];
                ldm_x4_t(vfm, vbase + voff + krow + (uint32_t)(db * 32));
                uint32_t b0[2] = { vfm[0], vfm[1] };
                uint32_t b1[2] = { vfm[2], vfm[3] };
                mma_16n8k16_f16(o[2 * db    ], pfrag[k16], b0);
                mma_16n8k16_f16(o[2 * db + 1], pfrag[k16], b1);
            }
            uint32_t ofm[2];
            ldm_x2_t(ofm, vbase + voff1 + krow);
            mma_16n8k16_f16(o9, pfrag[k16], ofm);
        }
    }

    // ---- epilogue: l from ones-column, fp16 Ctx ----
    const float inv0 = 1.f / o9[0];
    const float inv1 = 1.f / o9[2];
    const int grow0 = qt * FQ + r0;
    const int grow1 = qt * FQ + r1;
    #pragma unroll
    for (int nb = 0; nb < 8; nb++) {
        const int d = nb * 8 + 2 * tig;
        *(uint32_t*)&g_Ctx[((size_t)(b * SS + grow0)) * DMODEL + h * DKH + d] =
            h2pk(o[nb][0] * inv0, o[nb][1] * inv0);
        *(uint32_t*)&g_Ctx[((size_t)(b * SS + grow1)) * DMODEL + h * DKH + d] =
            h2pk(o[nb][2] * inv1, o[nb][3] * inv1);
    }
}

// ---------------------------------------------------------------------------
extern "C" void kernel_launch(void* const* d_in, const int* in_sizes, int n_in,
                              void* d_out, int out_size)
{
    const float* q    = (const float*)d_in[0];
    const float* k    = (const float*)d_in[1];
    const float* v    = (const float*)d_in[2];
    const int*   mask = (const int*)  d_in[3];
    const float* wq   = (const float*)d_in[4];
    const float* bq   = (const float*)d_in[5];
    const float* wk   = (const float*)d_in[6];
    const float* bk   = (const float*)d_in[7];
    const float* wv   = (const float*)d_in[8];
    const float* bv   = (const float*)d_in[9];
    const float* wo   = (const float*)d_in[10];
    const float* bo   = (const float*)d_in[11];
    float* out = (float*)d_out;

    (void)cudaFuncSetAttribute(flash_attn_mma_kernel,
                               cudaFuncAttributeMaxDynamicSharedMemorySize,
                               ATTN2_SMEM_BYTES);
    (void)cudaFuncSetAttribute(gemm_qkv_kernel,
                               cudaFuncAttributeMaxDynamicSharedMemorySize,
                               GEMM_SMEM_BYTES);
    (void)cudaFuncSetAttribute(gemm_out_kernel,
                               cudaFuncAttributeMaxDynamicSharedMemorySize,
                               GEMM_SMEM_BYTES);

    dim3 gc1(MTOK * DMODEL / (256 * 8), 3);   // (4096, 3)
    cvt_qkv_kernel<<<gc1, 256>>>(q, k, v);
    dim3 gc2(DMODEL * DMODEL / (256 * 8), 4); // (512, 4)
    cvt_w_kernel<<<gc2, 256>>>(wq, wk, wv, wo);
    cvt_mask_kernel<<<BB * SS / 256, 256>>>(mask);

    dim3 gq(MTOK/128, DMODEL/128, 3);   // (64, 8, 3)
    gemm_qkv_kernel<<<gq, 256, GEMM_SMEM_BYTES>>>(bq, bk, bv);

    dim3 ga(SS/FQ, BB*NH);              // (16, 64)
    flash_attn_mma_kernel<<<ga, 256, ATTN2_SMEM_BYTES>>>();

    dim3 gg(MTOK/128, DMODEL/128);      // (64, 8)
    gemm_out_kernel<<<gg, 256, GEMM_SMEM_BYTES>>>(bo, out);
}

// round 16
// speedup vs baseline: 1.1571x; 1.0065x over previous
#include <cuda_runtime.h>
#include <cuda_fp16.h>
#include <cstdint>
#include <math.h>

#define BB   4
#define SS   2048
#define DMODEL 1024
#define NH   16
#define DKH  64
#define MTOK (BB*SS)   // 8192

// 0.125 * log2(e): folds score scale + exp->exp2 conversion into Q projection
#define QSCALE 0.18033688011112042f

// fp16 scratch (device globals: allocation-free).
__device__ __half g_q16[MTOK * DMODEL];
__device__ __half g_k16[MTOK * DMODEL];
__device__ __half g_v16[MTOK * DMODEL];
__device__ __half g_w16[4 * DMODEL * DMODEL];   // wq, wk, wv, wo
__device__ __half g_Qh [MTOK * DMODEL];
__device__ __half g_Kh [MTOK * DMODEL];
__device__ __half g_Vh [MTOK * DMODEL];
__device__ __half g_Ctx[MTOK * DMODEL];
__device__ __half g_mkh[BB * SS];               // +inf (keep) / -inf (masked)

// ---------------------------------------------------------------------------
// helpers (baseline PTX; no sm_103a-only features)
// ---------------------------------------------------------------------------
__device__ __forceinline__ uint32_t h2pk(float lo, float hi) {
    __half2 h = __halves2half2(__float2half_rn(lo), __float2half_rn(hi));
    return *(uint32_t*)&h;
}

__device__ __forceinline__ uint32_t cvt2h(float hi, float lo) {
    uint32_t r;
    asm("cvt.rn.f16x2.f32 %0, %1, %2;" : "=r"(r) : "f"(hi), "f"(lo));
    return r;
}

__device__ __forceinline__ uint32_t hmin2(uint32_t a, uint32_t b) {
    uint32_t r;
    asm("min.f16x2 %0, %1, %2;" : "=r"(r) : "r"(a), "r"(b));
    return r;
}

__device__ __forceinline__ uint32_t hex2(uint32_t a) {
    uint32_t r;
    asm("ex2.approx.f16x2 %0, %1;" : "=r"(r) : "r"(a));
    return r;
}

__device__ __forceinline__ void mma_16n8k16_f16(float* d, const uint32_t* a,
                                                const uint32_t* b) {
    asm volatile(
        "mma.sync.aligned.m16n8k16.row.col.f32.f16.f16.f32 "
        "{%0,%1,%2,%3}, {%4,%5,%6,%7}, {%8,%9}, {%0,%1,%2,%3};\n"
        : "+f"(d[0]), "+f"(d[1]), "+f"(d[2]), "+f"(d[3])
        : "r"(a[0]), "r"(a[1]), "r"(a[2]), "r"(a[3]),
          "r"(b[0]), "r"(b[1]));
}

__device__ __forceinline__ void ldm_x4(uint32_t* r, uint32_t saddr) {
    asm volatile(
        "ldmatrix.sync.aligned.m8n8.x4.shared.b16 {%0,%1,%2,%3}, [%4];"
        : "=r"(r[0]), "=r"(r[1]), "=r"(r[2]), "=r"(r[3]) : "r"(saddr));
}

__device__ __forceinline__ void ldm_x4_t(uint32_t* r, uint32_t saddr) {
    asm volatile(
        "ldmatrix.sync.aligned.m8n8.x4.trans.shared.b16 {%0,%1,%2,%3}, [%4];"
        : "=r"(r[0]), "=r"(r[1]), "=r"(r[2]), "=r"(r[3]) : "r"(saddr));
}

__device__ __forceinline__ void ldm_x2_t(uint32_t* r, uint32_t saddr) {
    asm volatile(
        "ldmatrix.sync.aligned.m8n8.x2.trans.shared.b16 {%0,%1}, [%2];"
        : "=r"(r[0]), "=r"(r[1]) : "r"(saddr));
}

__device__ __forceinline__ void cp16(uint32_t smem, const void* g) {
    asm volatile("cp.async.cg.shared.global [%0], [%1], 16;\n"
                 :: "r"(smem), "l"(g));
}
#define CP_COMMIT() asm volatile("cp.async.commit_group;\n" ::: "memory")
#define CP_WAIT0()  asm volatile("cp.async.wait_group 0;\n" ::: "memory")

// ---------------------------------------------------------------------------
// one-time conversion kernels
// ---------------------------------------------------------------------------
__global__ __launch_bounds__(256)
void cvt_qkv_kernel(const float* __restrict__ q, const float* __restrict__ k,
                    const float* __restrict__ v)
{
    const float* in = (blockIdx.y == 0) ? q : (blockIdx.y == 1) ? k : v;
    __half* out = (blockIdx.y == 0) ? g_q16 : (blockIdx.y == 1) ? g_k16 : g_v16;
    const size_t i = ((size_t)blockIdx.x * 256 + threadIdx.x) * 8;
    float4 a = *(const float4*)(in + i);
    float4 b = *(const float4*)(in + i + 4);
    *(uint4*)(out + i) = make_uint4(h2pk(a.x, a.y), h2pk(a.z, a.w),
                                    h2pk(b.x, b.y), h2pk(b.z, b.w));
}

__global__ __launch_bounds__(256)
void cvt_w_kernel(const float* __restrict__ wq, const float* __restrict__ wk,
                  const float* __restrict__ wv, const float* __restrict__ wo)
{
    const float* in = (blockIdx.y == 0) ? wq : (blockIdx.y == 1) ? wk
                    : (blockIdx.y == 2) ? wv : wo;
    __half* out = g_w16 + (size_t)blockIdx.y * DMODEL * DMODEL;
    const size_t i = ((size_t)blockIdx.x * 256 + threadIdx.x) * 8;
    float4 a = *(const float4*)(in + i);
    float4 b = *(const float4*)(in + i + 4);
    *(uint4*)(out + i) = make_uint4(h2pk(a.x, a.y), h2pk(a.z, a.w),
                                    h2pk(b.x, b.y), h2pk(b.z, b.w));
}

__global__ __launch_bounds__(256)
void cvt_mask_kernel(const int* __restrict__ mask)
{
    const int i = blockIdx.x * 256 + threadIdx.x;   // 8192 total
    const unsigned short bits = mask[i] ? 0x7C00u : 0xFC00u;   // +inf / -inf
    *(unsigned short*)&g_mkh[i] = bits;
}

// ===========================================================================
// GEMM fp16 m16n8k16, BK=64 (16 stages), double-buffered cp.async,
// ldmatrix frags. CTA 128x128, 8 warps 4(m)x2(n), warp 32x64.
// Smem stride 72 halves (144 B).  (R15-best config.)
// ===========================================================================
#define GPH   72
#define GSTG  (128 * GPH)             // 9216 halves per operand-stage
#define GEMM_SMEM_BYTES (4 * GSTG * 2)   // A0,A1,B0,B1 = 73728 B

__device__ __forceinline__ void gemm_issue(uint32_t sb, const __half* Ap,
                                           const __half* Bp, int tid,
                                           int k0, int st)
{
    #pragma unroll
    for (int i = 0; i < 4; i++) {
        const int fi  = tid + 256 * i;      // 0..1023
        const int row = fi >> 3;            // 0..127
        const int c   = fi & 7;             // 8 halves per chunk
        cp16(sb + (uint32_t)((st * GSTG + row * GPH + c * 8) * 2),
             Ap + (size_t)row * DMODEL + k0 + c * 8);
        cp16(sb + (uint32_t)(((2 + st) * GSTG + row * GPH + c * 8) * 2),
             Bp + (size_t)row * DMODEL + k0 + c * 8);
    }
}

// MODE 0: fp32 flat out. MODE 1: fp16 head-split out (scaled by outscale).
template<int MODE>
__device__ __forceinline__ void gemm_core(const __half* __restrict__ X,
                                          const __half* __restrict__ W,
                                          const float* __restrict__ bias,
                                          void* __restrict__ outv,
                                          float outscale,
                                          __half* smh)
{
    const int tid  = threadIdx.x;
    const int wid  = tid >> 5;
    const int lane = tid & 31;
    const int gid  = lane >> 2;
    const int tig  = lane & 3;
    const int wm   = wid >> 1;
    const int wn   = wid & 1;
    const int lr   = lane & 15;
    const int lc8  = (lane >> 4) * 8;

    const int m0 = blockIdx.x * 128;
    const int n0 = blockIdx.y * 128;

    const __half* Ap = X + (size_t)m0 * DMODEL;
    const __half* Bp = W + (size_t)n0 * DMODEL;

    const uint32_t sbase = (uint32_t)__cvta_generic_to_shared(smh);
    uint32_t aoff[2], boff[4];
    #pragma unroll
    for (int mi = 0; mi < 2; mi++)
        aoff[mi] = (uint32_t)(((wm * 32 + mi * 16 + lr) * GPH + lc8) * 2);
    #pragma unroll
    for (int njp = 0; njp < 4; njp++)
        boff[njp] = (uint32_t)((2 * GSTG + (wn * 64 + njp * 16 + lr) * GPH + lc8) * 2);

    float acc[2][8][4];
    #pragma unroll
    for (int mi = 0; mi < 2; mi++)
        #pragma unroll
        for (int nj = 0; nj < 8; nj++)
            #pragma unroll
            for (int c = 0; c < 4; c++) acc[mi][nj][c] = 0.f;

    gemm_issue(sbase, Ap, Bp, tid, 0, 0);
    CP_COMMIT();

    for (int s = 0; s < 16; s++) {
        CP_WAIT0();
        __syncthreads();
        if (s + 1 < 16) {
            gemm_issue(sbase, Ap, Bp, tid, (s + 1) * 64, (s + 1) & 1);
            CP_COMMIT();
        }

        const int st = s & 1;
        const uint32_t abuf = sbase + (uint32_t)(st * GSTG * 2);
        const uint32_t bb   = (uint32_t)(st * GSTG * 2);

        #pragma unroll
        for (int k16 = 0; k16 < 4; k16++) {
            const uint32_t kb = (uint32_t)(k16 * 32);
            uint32_t af[2][4];
            ldm_x4(af[0], abuf + aoff[0] + kb);
            ldm_x4(af[1], abuf + aoff[1] + kb);
            #pragma unroll
            for (int njp = 0; njp < 4; njp++) {
                uint32_t bfm[4];
                ldm_x4(bfm, sbase + bb + boff[njp] + kb);
                uint32_t b0[2] = { bfm[0], bfm[2] };
                uint32_t b1[2] = { bfm[1], bfm[3] };
                mma_16n8k16_f16(acc[0][2 * njp    ], af[0], b0);
                mma_16n8k16_f16(acc[1][2 * njp    ], af[1], b0);
                mma_16n8k16_f16(acc[0][2 * njp + 1], af[0], b1);
                mma_16n8k16_f16(acc[1][2 * njp + 1], af[1], b1);
            }
        }
    }

    #pragma unroll
    for (int mi = 0; mi < 2; mi++) {
        #pragma unroll
        for (int half = 0; half < 2; half++) {
            const int m = m0 + wm * 32 + mi * 16 + gid + half * 8;
            #pragma unroll
            for (int nj = 0; nj < 8; nj++) {
                const int n = n0 + wn * 64 + nj * 8 + tig * 2;
                float ox = acc[mi][nj][half * 2 + 0] + __ldg(&bias[n + 0]);
                float oy = acc[mi][nj][half * 2 + 1] + __ldg(&bias[n + 1]);
                if (MODE == 0) {
                    float* dst = (float*)outv + (size_t)m * DMODEL + n;
                    *(float2*)dst = make_float2(ox, oy);
                } else {
                    ox *= outscale; oy *= outscale;
                    const int b = m >> 11, s2 = m & (SS - 1);
                    const int h = n >> 6,  d  = n & (DKH - 1);
                    __half* dst = (__half*)outv +
                        (((size_t)(b * NH + h) * SS) + s2) * DKH + d;
                    *(uint32_t*)dst = h2pk(ox, oy);
                }
            }
        }
    }
}

__global__ __launch_bounds__(256, 2)
void gemm_qkv_kernel(const float* __restrict__ bq, const float* __restrict__ bk,
                     const float* __restrict__ bv)
{
    extern __shared__ __half smg[];
    const int z = blockIdx.z;
    const __half* X = (z == 0) ? g_q16 : (z == 1) ? g_k16 : g_v16;
    const __half* W = g_w16 + (size_t)z * DMODEL * DMODEL;
    const float* B = (z == 0) ? bq : (z == 1) ? bk : bv;
    __half* O = (z == 0) ? g_Qh : (z == 1) ? g_Kh : g_Vh;
    const float sc = (z == 0) ? QSCALE : 1.0f;
    gemm_core<1>(X, W, B, O, sc, smg);
}

__global__ __launch_bounds__(256, 2)
void gemm_out_kernel(const float* __restrict__ bias, float* __restrict__ out)
{
    extern __shared__ __half smg[];
    gemm_core<0>(g_Ctx, g_w16 + (size_t)3 * DMODEL * DMODEL, bias, out, 1.0f, smg);
}

// ===========================================================================
// Flash attention fp16 m16n8k16, static-C softmax, mask via min.f16x2,
// p = ex2.approx.f16x2 into A-frag, row sums via ones-column MMA.
// 128-KEY double buffers (two 64-key sub-tiles per sync) -> 16 barriers.
// ===========================================================================
#define FQ   128
#define FKB  128                      // keys per buffer
#define AP2  72
#define QTILE (FQ*AP2)                // 9216 halves
#define KBUF  (FKB*AP2)               // 9216 halves
#define SM_QS 0
#define SM_KS QTILE                   // 9216
#define SM_VS (SM_KS + 2*KBUF)        // 27648
#define SM_MK (SM_VS + 2*KBUF)        // 46080 halves
#define ATTN2_SMEM_BYTES ((SM_MK + 256) * 2 + 256)   // ~92.9 KB

__device__ __forceinline__ void attn_issue(uint32_t sb, const __half* Kb,
                                           const __half* Vb, const __half* mb,
                                           int tid, int kt2, int buf)
{
    // load 128 rows of K and V (kt2 indexes 128-key blocks)
    #pragma unroll
    for (int i = 0; i < 4; i++) {
        const int fi  = tid + 256 * i;      // 0..1023
        const int row = fi >> 3;            // 0..127
        const int c   = fi & 7;
        cp16(sb + (uint32_t)((SM_KS + buf * KBUF + row * AP2 + c * 8) * 2),
             Kb + (size_t)(kt2 * FKB + row) * DKH + c * 8);
        cp16(sb + (uint32_t)((SM_VS + buf * KBUF + row * AP2 + c * 8) * 2),
             Vb + (size_t)(kt2 * FKB + row) * DKH + c * 8);
    }
    if (tid < 16)
        cp16(sb + (uint32_t)((SM_MK + buf * 128 + tid * 8) * 2),
             mb + kt2 * 128 + tid * 8);
}

__global__ __launch_bounds__(256, 2)
void flash_attn_mma_kernel()
{
    extern __shared__ __half smh[];
    __half* mskh = smh + SM_MK;       // mskh[buf*128 + c], +-inf

    const int qt = blockIdx.x;
    const int bh = blockIdx.y;
    const int b  = bh >> 4;
    const int h  = bh & 15;

    const __half* Qb = g_Qh + (size_t)bh * SS * DKH;
    const __half* Kb = g_Kh + (size_t)bh * SS * DKH;
    const __half* Vb = g_Vh + (size_t)bh * SS * DKH;
    const __half* mb = g_mkh + b * SS;

    const int tid  = threadIdx.x;
    const int wid  = tid >> 5;
    const int lane = tid & 31;
    const int gid  = lane >> 2;
    const int tig  = lane & 3;
    const int r0   = wid * 16 + gid;
    const int r1   = r0 + 8;
    const int lr   = lane & 15;
    const int lc8  = (lane >> 4) * 8;

    const uint32_t sbase = (uint32_t)__cvta_generic_to_shared(smh);
    const uint32_t qoff  = sbase + (uint32_t)(((wid * 16 + lr) * AP2 + lc8) * 2);
    uint32_t koff[4];
    #pragma unroll
    for (int nbp = 0; nbp < 4; nbp++)
        koff[nbp] = (uint32_t)(((nbp * 16 + lr) * AP2 + lc8) * 2);
    const int vg  = lane >> 3;
    const int vl7 = lane & 7;
    const uint32_t voff  = (uint32_t)((((vg & 1) * 8 + vl7) * AP2 + (vg >> 1) * 8) * 2);
    const uint32_t voff1 = (uint32_t)((((vg & 1) * 8 + vl7) * AP2 + 64) * 2);

    // prologue: 128-key block 0 via cp.async
    attn_issue(sbase, Kb, Vb, mb, tid, 0, 0);
    CP_COMMIT();

    // Q tile copy (fp16, pre-scaled by QSCALE in projection)
    #pragma unroll
    for (int i = 0; i < 4; i++) {
        const int fi  = tid + 256 * i;
        const int row = fi >> 3;
        const int c   = fi & 7;
        *(uint4*)&smh[SM_QS + (size_t)row * AP2 + c * 8] =
            *(const uint4*)(Qb + (size_t)(qt * FQ + row) * DKH + c * 8);
    }
    // ones padding in V cols 64..71 (both 128-row buffers) — row-sum column
    {
        const uint32_t one2 = 0x3C003C00u;   // half2(1.0, 1.0)
        for (int i = tid; i < 2 * FKB * 4; i += 256) {
            const int buf = i >> 9;           // 0..1
            const int row = (i >> 2) & 127;
            const int c2  = i & 3;
            *(uint32_t*)&smh[SM_VS + buf * KBUF + row * AP2 + 64 + c2 * 2] = one2;
        }
    }

    float o[8][4], o9[4];
    #pragma unroll
    for (int nb = 0; nb < 8; nb++)
        #pragma unroll
        for (int c = 0; c < 4; c++) o[nb][c] = 0.f;
    #pragma unroll
    for (int c = 0; c < 4; c++) o9[c] = 0.f;

    const int NT2 = SS / FKB;   // 16
    for (int kt = 0; kt < NT2; kt++) {
        const int cur = kt & 1;
        CP_WAIT0();
        __syncthreads();
        if (kt + 1 < NT2) {
            attn_issue(sbase, Kb, Vb, mb, tid, kt + 1, 1 - cur);
            CP_COMMIT();
        }

        #pragma unroll
        for (int h2 = 0; h2 < 2; h2++) {
            const uint32_t kbase = sbase +
                (uint32_t)((SM_KS + cur * KBUF + h2 * 64 * AP2) * 2);
            const uint32_t vbase = sbase +
                (uint32_t)((SM_VS + cur * KBUF + h2 * 64 * AP2) * 2);
            const __half* mc = mskh + cur * 128 + h2 * 64;

            // ---- S = Q K^T (log2 domain) ----
            float sa[8][4];
            #pragma unroll
            for (int nb = 0; nb < 8; nb++)
                #pragma unroll
                for (int c = 0; c < 4; c++) sa[nb][c] = 0.f;

            #pragma unroll
            for (int k16 = 0; k16 < 4; k16++) {
                const uint32_t kb = (uint32_t)(k16 * 32);
                uint32_t af[4];
                ldm_x4(af, qoff + kb);
                #pragma unroll
                for (int nbp = 0; nbp < 4; nbp++) {
                    uint32_t bfm[4];
                    ldm_x4(bfm, kbase + koff[nbp] + kb);
                    uint32_t b0[2] = { bfm[0], bfm[2] };
                    uint32_t b1[2] = { bfm[1], bfm[3] };
                    mma_16n8k16_f16(sa[2 * nbp    ], af, b0);
                    mma_16n8k16_f16(sa[2 * nbp + 1], af, b1);
                }
            }

            // ---- static-C softmax: p = exp2(min(s, maskinf)) ----
            uint32_t pfrag[4][4];
            #pragma unroll
            for (int nb = 0; nb < 8; nb++) {
                const int c0 = nb * 8 + 2 * tig;
                const uint32_t m2 = *(const uint32_t*)&mc[c0];
                uint32_t s0 = cvt2h(sa[nb][1], sa[nb][0]);
                uint32_t s1 = cvt2h(sa[nb][3], sa[nb][2]);
                const uint32_t p0 = hex2(hmin2(s0, m2));
                const uint32_t p1 = hex2(hmin2(s1, m2));
                const int kb2 = nb >> 1;
                if ((nb & 1) == 0) {
                    pfrag[kb2][0] = p0;
                    pfrag[kb2][1] = p1;
                } else {
                    pfrag[kb2][2] = p0;
                    pfrag[kb2][3] = p1;
                }
            }

            // ---- O += P V ; row sums into o9 via ones-column ----
            #pragma unroll
            for (int k16 = 0; k16 < 4; k16++) {
                const uint32_t krow = (uint32_t)(k16 * 16 * AP2 * 2);
                #pragma unroll
                for (int db = 0; db < 4; db++) {
                    uint32_t vfm[4];
                    ldm_x4_t(vfm, vbase + voff + krow + (uint32_t)(db * 32));
                    uint32_t b0[2] = { vfm[0], vfm[1] };
                    uint32_t b1[2] = { vfm[2], vfm[3] };
                    mma_16n8k16_f16(o[2 * db    ], pfrag[k16], b0);
                    mma_16n8k16_f16(o[2 * db + 1], pfrag[k16], b1);
                }
                uint32_t ofm[2];
                ldm_x2_t(ofm, vbase + voff1 + krow);
                mma_16n8k16_f16(o9, pfrag[k16], ofm);
            }
        }
    }

    // ---- epilogue: l from ones-column, fp16 Ctx ----
    const float inv0 = 1.f / o9[0];
    const float inv1 = 1.f / o9[2];
    const int grow0 = qt * FQ + r0;
    const int grow1 = qt * FQ + r1;
    #pragma unroll
    for (int nb = 0; nb < 8; nb++) {
        const int d = nb * 8 + 2 * tig;
        *(uint32_t*)&g_Ctx[((size_t)(b * SS + grow0)) * DMODEL + h * DKH + d] =
            h2pk(o[nb][0] * inv0, o[nb][1] * inv0);
        *(uint32_t*)&g_Ctx[((size_t)(b * SS + grow1)) * DMODEL + h * DKH + d] =
            h2pk(o[nb][2] * inv1, o[nb][3] * inv1);
    }
}

// ---------------------------------------------------------------------------
extern "C" void kernel_launch(void* const* d_in, const int* in_sizes, int n_in,
                              void* d_out, int out_size)
{
    const float* q    = (const float*)d_in[0];
    const float* k    = (const float*)d_in[1];
    const float* v    = (const float*)d_in[2];
    const int*   mask = (const int*)  d_in[3];
    const float* wq   = (const float*)d_in[4];
    const float* bq   = (const float*)d_in[5];
    const float* wk   = (const float*)d_in[6];
    const float* bk   = (const float*)d_in[7];
    const float* wv   = (const float*)d_in[8];
    const float* bv   = (const float*)d_in[9];
    const float* wo   = (const float*)d_in[10];
    const float* bo   = (const float*)d_in[11];
    float* out = (float*)d_out;

    (void)cudaFuncSetAttribute(flash_attn_mma_kernel,
                               cudaFuncAttributeMaxDynamicSharedMemorySize,
                               ATTN2_SMEM_BYTES);
    (void)cudaFuncSetAttribute(gemm_qkv_kernel,
                               cudaFuncAttributeMaxDynamicSharedMemorySize,
                               GEMM_SMEM_BYTES);
    (void)cudaFuncSetAttribute(gemm_out_kernel,
                               cudaFuncAttributeMaxDynamicSharedMemorySize,
                               GEMM_SMEM_BYTES);

    dim3 gc1(MTOK * DMODEL / (256 * 8), 3);   // (4096, 3)
    cvt_qkv_kernel<<<gc1, 256>>>(q, k, v);
    dim3 gc2(DMODEL * DMODEL / (256 * 8), 4); // (512, 4)
    cvt_w_kernel<<<gc2, 256>>>(wq, wk, wv, wo);
    cvt_mask_kernel<<<BB * SS / 256, 256>>>(mask);

    dim3 gq(MTOK/128, DMODEL/128, 3);   // (64, 8, 3)
    gemm_qkv_kernel<<<gq, 256, GEMM_SMEM_BYTES>>>(bq, bk, bv);

    dim3 ga(SS/FQ, BB*NH);              // (16, 64)
    flash_attn_mma_kernel<<<ga, 256, ATTN2_SMEM_BYTES>>>();

    dim3 gg(MTOK/128, DMODEL/128);      // (64, 8)
    gemm_out_kernel<<<gg, 256, GEMM_SMEM_BYTES>>>(bo, out);
}